// round 2
// baseline (speedup 1.0000x reference)
#include <cuda_runtime.h>

// Problem constants
#define BDIM   64
#define CIN    256
#define COUT   256
#define CS     256
#define HIDDEN 64
#define KEXP   4
#define LDIM   1024
#define TEMPR  30.0f

// Conv tiling
#define OTILE  32
#define ICCH   16
#define LCH    256

// Routing weights (softmax attention per sample), computed by att_kernel
__device__ float g_att[BDIM * KEXP];

// ---------------------------------------------------------------------------
// Kernel 1: routing MLP + softmax.  One block per sample, 64 threads.
//   h = relu(w1 @ cond_b)   (HIDDEN=64 dots of CS=256)
//   logits = w2 @ h         (K=4 dots of 64)
//   att = softmax(logits / TEMP)
// ---------------------------------------------------------------------------
__global__ void att_kernel(const float* __restrict__ cond,
                           const float* __restrict__ w1,
                           const float* __restrict__ w2) {
    int b = blockIdx.x;
    int j = threadIdx.x;  // 0..63
    __shared__ float h[HIDDEN];
    __shared__ float logits[KEXP];

    const float* cb  = cond + b * CS;
    const float* w1j = w1 + j * CS;
    float acc = 0.f;
    #pragma unroll 8
    for (int c = 0; c < CS; c++) acc = fmaf(w1j[c], cb[c], acc);
    h[j] = fmaxf(acc, 0.f);
    __syncthreads();

    if (j < KEXP) {
        const float* w2j = w2 + j * HIDDEN;
        float s = 0.f;
        #pragma unroll 8
        for (int c = 0; c < HIDDEN; c++) s = fmaf(w2j[c], h[c], s);
        logits[j] = s / TEMPR;
    }
    __syncthreads();

    if (j == 0) {
        float m = logits[0];
        #pragma unroll
        for (int k = 1; k < KEXP; k++) m = fmaxf(m, logits[k]);
        float e[KEXP];
        float ssum = 0.f;
        #pragma unroll
        for (int k = 0; k < KEXP; k++) { e[k] = expf(logits[k] - m); ssum += e[k]; }
        float inv = 1.f / ssum;
        #pragma unroll
        for (int k = 0; k < KEXP; k++) g_att[b * KEXP + k] = e[k] * inv;
    }
}

// ---------------------------------------------------------------------------
// Kernel 2: per-sample dynamic 1-D 3-tap conv (the 3x3 conv on (L,1) input
// reduces to the middle kernel column; side columns hit zero padding).
//
// Block = (sample b, 32 output channels).  256 threads:
//   warp = one group of 4 output channels (weight LDS are broadcasts)
//   lane = L position, each thread owns 8 L positions strided by 32
//          (conflict-free x LDS, coalesced output stores)
// Expert aggregation (sum over 4 experts weighted by att) is done on the fly
// while filling the weight tile in shared memory — the 9.4 MB weight tensor
// stays L2-resident across the 512 blocks.
// ---------------------------------------------------------------------------
__global__ __launch_bounds__(256, 2)
void conv_kernel(const float* __restrict__ x,
                 const float* __restrict__ weight,
                 const float* __restrict__ bias,
                 float* __restrict__ out) {
    __shared__ float xs[ICCH][LCH + 2];
    __shared__ float ws[ICCH][OTILE][3];

    const int b   = blockIdx.y;
    const int o0  = blockIdx.x * OTILE;
    const int tid = threadIdx.x;
    const int lg  = tid & 31;        // lane -> L offset
    const int ol  = (tid >> 5) * 4;  // warp -> output-channel group base

    const float a0 = g_att[b * 4 + 0];
    const float a1 = g_att[b * 4 + 1];
    const float a2 = g_att[b * 4 + 2];
    const float a3 = g_att[b * 4 + 3];

    // Aggregated bias for this thread's 4 output channels
    float bb[4];
    #pragma unroll
    for (int oo = 0; oo < 4; oo++) {
        int o = o0 + ol + oo;
        bb[oo] = a0 * bias[0 * COUT + o] + a1 * bias[1 * COUT + o]
               + a2 * bias[2 * COUT + o] + a3 * bias[3 * COUT + o];
    }

    const long estride = (long)COUT * CIN * 9;  // expert stride in weight tensor

    for (int l0 = 0; l0 < LDIM; l0 += LCH) {
        float acc[4][8];
        #pragma unroll
        for (int oo = 0; oo < 4; oo++)
            #pragma unroll
            for (int j = 0; j < 8; j++) acc[oo][j] = 0.f;

        for (int i0 = 0; i0 < CIN; i0 += ICCH) {
            __syncthreads();  // previous tile fully consumed

            // Fill aggregated weight tile: ws[r][o][t] = sum_k att_k * W[k][o0+o][i0+r][t][1]
            for (int e = tid; e < ICCH * OTILE * 3; e += 256) {
                int r   = e / (OTILE * 3);
                int rem = e % (OTILE * 3);
                int o   = rem / 3;
                int t   = rem % 3;
                long base = ((long)(o0 + o) * CIN + (i0 + r)) * 9 + t * 3 + 1;
                float v = a0 * __ldg(weight + base)
                        + a1 * __ldg(weight + base + estride)
                        + a2 * __ldg(weight + base + 2 * estride)
                        + a3 * __ldg(weight + base + 3 * estride);
                ws[r][o][t] = v;
            }

            // Stage x tile with halo: xs[r][c] = x[b][i0+r][l0 + c - 1]
            for (int e = tid; e < ICCH * (LCH + 2); e += 256) {
                int r  = e / (LCH + 2);
                int c  = e % (LCH + 2);
                int gl = l0 + c - 1;
                float v = 0.f;
                if (gl >= 0 && gl < LDIM)
                    v = x[((long)(b * CIN + i0 + r)) * LDIM + gl];
                xs[r][c] = v;
            }
            __syncthreads();

            #pragma unroll
            for (int r = 0; r < ICCH; r++) {
                float w[4][3];
                #pragma unroll
                for (int oo = 0; oo < 4; oo++) {
                    w[oo][0] = ws[r][ol + oo][0];
                    w[oo][1] = ws[r][ol + oo][1];
                    w[oo][2] = ws[r][ol + oo][2];
                }
                #pragma unroll
                for (int j = 0; j < 8; j++) {
                    int ll = lg + 32 * j;
                    float x0 = xs[r][ll];
                    float x1 = xs[r][ll + 1];
                    float x2 = xs[r][ll + 2];
                    #pragma unroll
                    for (int oo = 0; oo < 4; oo++) {
                        acc[oo][j] = fmaf(w[oo][0], x0, acc[oo][j]);
                        acc[oo][j] = fmaf(w[oo][1], x1, acc[oo][j]);
                        acc[oo][j] = fmaf(w[oo][2], x2, acc[oo][j]);
                    }
                }
            }
        }

        // Write this L chunk (coalesced: lanes consecutive in l)
        #pragma unroll
        for (int oo = 0; oo < 4; oo++) {
            float* op = out + ((long)(b * COUT + o0 + ol + oo)) * LDIM + l0;
            #pragma unroll
            for (int j = 0; j < 8; j++)
                op[lg + 32 * j] = acc[oo][j] + bb[oo];
        }
    }
}

// ---------------------------------------------------------------------------
extern "C" void kernel_launch(void* const* d_in, const int* in_sizes, int n_in,
                              void* d_out, int out_size) {
    const float* x      = (const float*)d_in[0];  // (64,256,1024,1)
    const float* cond   = (const float*)d_in[1];  // (64,256)
    const float* w1     = (const float*)d_in[2];  // (64,256)
    const float* w2     = (const float*)d_in[3];  // (4,64)
    const float* weight = (const float*)d_in[4];  // (4,256,256,3,3)
    const float* bias   = (const float*)d_in[5];  // (4,256)
    float* out = (float*)d_out;                   // (64,256,1024,1)

    att_kernel<<<BDIM, HIDDEN>>>(cond, w1, w2);
    dim3 grid(COUT / OTILE, BDIM);
    conv_kernel<<<grid, 256>>>(x, weight, bias, out);
}